// round 1
// baseline (speedup 1.0000x reference)
#include <cuda_runtime.h>
#include <cstdint>

// Problem constants (from reference): N=100000, F=512, H=16, C=40, E=3200000
#define NMAX 100000
#define EMAX 3200000
#define FDIM 512
#define HDIM 16
#define CDIM 40

// ---- scratch (static device globals; no allocation allowed) ----
__device__ int   g_is64;
__device__ int   g_src[EMAX];
__device__ int   g_dst[EMAX];
__device__ float g_norm[EMAX];
__device__ int   g_deg[NMAX];
__device__ float g_dinv[NMAX];
__device__ float g_h1[NMAX * HDIM];    // x@W1, then gather source for prop1
__device__ float g_agg1[NMAX * HDIM];  // prop1 accum -> relu(.+b1) in place
__device__ float g_agg2[NMAX * HDIM];  // prop2 accum

// ---------------------------------------------------------------
// Detect whether edge_index buffer is int64 or int32.
// Values are node ids in [0, 1e5) so if stored as little-endian int64,
// every odd 32-bit word is 0. Probability of 128 consecutive random
// int32 node ids all being zero is ~0.
__global__ void k_detect(const int* __restrict__ ei) {
    if (threadIdx.x == 0 && blockIdx.x == 0) {
        int any = 0;
        #pragma unroll
        for (int i = 1; i < 256; i += 2) any |= ei[i];
        g_is64 = (any == 0) ? 1 : 0;
    }
}

__global__ void k_zero_deg(int N) {
    int i = blockIdx.x * blockDim.x + threadIdx.x;
    if (i < N) g_deg[i] = 0;
}

// Normalize edges to int32 src/dst and count in-degree (dst side).
__global__ void k_convert(const void* __restrict__ ei, int E) {
    int e = blockIdx.x * blockDim.x + threadIdx.x;
    if (e >= E) return;
    int s, d;
    if (g_is64) {
        const long long* p = (const long long*)ei;
        s = (int)p[e];
        d = (int)p[(long long)E + e];
    } else {
        const int* p = (const int*)ei;
        s = p[e];
        d = p[E + e];
    }
    g_src[e] = s;
    g_dst[e] = d;
    atomicAdd(&g_deg[d], 1);
}

__global__ void k_dinv(int N) {
    int i = blockIdx.x * blockDim.x + threadIdx.x;
    if (i < N) {
        // +1 for the self-loop; deg > 0 always.
        g_dinv[i] = rsqrtf((float)(g_deg[i] + 1));
    }
}

__global__ void k_norm(int E) {
    int e = blockIdx.x * blockDim.x + threadIdx.x;
    if (e < E) g_norm[e] = g_dinv[g_src[e]] * g_dinv[g_dst[e]];
}

// ---------------------------------------------------------------
// GEMM1: g_h1[N,16] = x[N,512] @ W1[512,16]
// Block = 256 threads = 8 warps; each warp computes 4 rows.
// W1 in shared with pitch 17 (odd) -> lane-stride-1 k access is
// conflict-free across the 32 banks.
__global__ __launch_bounds__(256) void k_gemm1(
    const float* __restrict__ x, const float* __restrict__ W1, int N)
{
    __shared__ float w[FDIM * 17];
    for (int i = threadIdx.x; i < FDIM * HDIM; i += 256)
        w[(i >> 4) * 17 + (i & 15)] = W1[i];
    __syncthreads();

    int warp = threadIdx.x >> 5;
    int lane = threadIdx.x & 31;
    int r0 = blockIdx.x * 32 + warp * 4;

    float acc[4][HDIM];
    #pragma unroll
    for (int r = 0; r < 4; r++)
        #pragma unroll
        for (int j = 0; j < HDIM; j++) acc[r][j] = 0.0f;

    bool v0 = (r0 + 0) < N, v1 = (r0 + 1) < N, v2 = (r0 + 2) < N, v3 = (r0 + 3) < N;

    #pragma unroll 4
    for (int i = 0; i < 16; i++) {
        int k = lane + 32 * i;
        float x0 = v0 ? x[(size_t)(r0 + 0) * FDIM + k] : 0.0f;
        float x1 = v1 ? x[(size_t)(r0 + 1) * FDIM + k] : 0.0f;
        float x2 = v2 ? x[(size_t)(r0 + 2) * FDIM + k] : 0.0f;
        float x3 = v3 ? x[(size_t)(r0 + 3) * FDIM + k] : 0.0f;
        const float* wr = &w[k * 17];
        #pragma unroll
        for (int j = 0; j < HDIM; j++) {
            float wv = wr[j];
            acc[0][j] += x0 * wv;
            acc[1][j] += x1 * wv;
            acc[2][j] += x2 * wv;
            acc[3][j] += x3 * wv;
        }
    }

    // full butterfly: every lane ends with the warp-sum
    #pragma unroll
    for (int r = 0; r < 4; r++)
        #pragma unroll
        for (int j = 0; j < HDIM; j++)
            #pragma unroll
            for (int off = 16; off; off >>= 1)
                acc[r][j] += __shfl_xor_sync(0xffffffffu, acc[r][j], off);

    // 64 outputs, 32 lanes -> 2 writes per lane
    {
        int idx = lane;           // (r, j)
        int r = idx >> 4, j = idx & 15;
        if (r0 + r < N) g_h1[(size_t)(r0 + r) * HDIM + j] = acc[r][j];
        idx = lane + 32;
        r = idx >> 4; j = idx & 15;
        if (r0 + r < N) g_h1[(size_t)(r0 + r) * HDIM + j] = acc[r][j];
    }
}

// ---------------------------------------------------------------
// Self-loop init: agg[i,:] = dinv[i]^2 * hin[i,:]
__global__ void k_self(int N, int layer) {
    int idx = blockIdx.x * blockDim.x + threadIdx.x;
    if (idx >= N * HDIM) return;
    const float* hin = layer ? g_agg1 : g_h1;
    float* out = layer ? g_agg2 : g_agg1;
    int i = idx >> 4;
    float dv = g_dinv[i];
    out[idx] = dv * dv * hin[idx];
}

// Edge propagation: 4 threads per edge, each handles a float4 chunk.
// agg[dst] += norm[e] * h[src] via vector red.
__global__ __launch_bounds__(256) void k_prop(int E, int layer) {
    int t = blockIdx.x * blockDim.x + threadIdx.x;
    int e = t >> 2;
    if (e >= E) return;
    int c = t & 3;
    const float4* hin = (const float4*)(layer ? g_agg1 : g_h1);
    float* out = layer ? g_agg2 : g_agg1;

    int s = g_src[e];
    int d = g_dst[e];
    float nr = g_norm[e];
    float4 v = hin[(size_t)s * 4 + c];
    v.x *= nr; v.y *= nr; v.z *= nr; v.w *= nr;
    float* p = out + (size_t)d * HDIM + c * 4;
    asm volatile("red.global.add.v4.f32 [%0], {%1, %2, %3, %4};"
                 :: "l"(p), "f"(v.x), "f"(v.y), "f"(v.z), "f"(v.w)
                 : "memory");
}

__global__ void k_biasrelu(const float* __restrict__ b1, int N) {
    int idx = blockIdx.x * blockDim.x + threadIdx.x;
    if (idx >= N * HDIM) return;
    float v = g_agg1[idx] + b1[idx & 15];
    g_agg1[idx] = v > 0.0f ? v : 0.0f;
}

// ---------------------------------------------------------------
// Output: logits = agg2 @ W2 + b2 ; out = softmax(logits)
// d_out[0 : N*40)         = softmax
// d_out[N*40 : 2*N*40)    = logits (tuple's second element)
__global__ __launch_bounds__(256) void k_out(
    const float* __restrict__ W2, const float* __restrict__ b2,
    float* __restrict__ dout, int N, int write_h)
{
    __shared__ float w[HDIM * CDIM];
    __shared__ float bs[CDIM];
    for (int i = threadIdx.x; i < HDIM * CDIM; i += blockDim.x) w[i] = W2[i];
    if (threadIdx.x < CDIM) bs[threadIdx.x] = b2[threadIdx.x];
    __syncthreads();

    int i = blockIdx.x * blockDim.x + threadIdx.x;
    if (i >= N) return;

    float row[HDIM];
    const float4* p = (const float4*)(g_agg2 + (size_t)i * HDIM);
    #pragma unroll
    for (int q = 0; q < 4; q++) {
        float4 v = p[q];
        row[q * 4 + 0] = v.x; row[q * 4 + 1] = v.y;
        row[q * 4 + 2] = v.z; row[q * 4 + 3] = v.w;
    }

    float logit[CDIM];
    #pragma unroll
    for (int j = 0; j < CDIM; j++) logit[j] = bs[j];
    #pragma unroll
    for (int k = 0; k < HDIM; k++) {
        float v = row[k];
        const float* wr = &w[k * CDIM];
        #pragma unroll
        for (int j = 0; j < CDIM; j++) logit[j] += v * wr[j];
    }

    float mx = logit[0];
    #pragma unroll
    for (int j = 1; j < CDIM; j++) mx = fmaxf(mx, logit[j]);
    float sum = 0.0f;
    #pragma unroll
    for (int j = 0; j < CDIM; j++) sum += __expf(logit[j] - mx);
    float inv = 1.0f / sum;

    float* so = dout + (size_t)i * CDIM;
    #pragma unroll
    for (int j = 0; j < CDIM; j++) so[j] = __expf(logit[j] - mx) * inv;

    if (write_h) {
        float* ho = dout + (size_t)N * CDIM + (size_t)i * CDIM;
        #pragma unroll
        for (int j = 0; j < CDIM; j++) ho[j] = logit[j];
    }
}

// ---------------------------------------------------------------
extern "C" void kernel_launch(void* const* d_in, const int* in_sizes, int n_in,
                              void* d_out, int out_size)
{
    // metadata order: x, edge_index, num_nodes, W1, b1, W2, b2
    const float* x  = (const float*)d_in[0];
    const void*  ei = d_in[1];
    const float* W1 = (const float*)d_in[3];
    const float* b1 = (const float*)d_in[4];
    const float* W2 = (const float*)d_in[5];
    const float* b2 = (const float*)d_in[6];
    float* out = (float*)d_out;

    int N = in_sizes[0] / FDIM;
    int E = in_sizes[1] / 2;
    if (N > NMAX) N = NMAX;
    if (E > EMAX) E = EMAX;
    int write_h = (out_size >= 2 * N * CDIM) ? 1 : 0;

    const int B = 256;

    k_detect<<<1, 32>>>((const int*)ei);
    k_zero_deg<<<(N + B - 1) / B, B>>>(N);
    k_convert<<<(E + B - 1) / B, B>>>(ei, E);
    k_dinv<<<(N + B - 1) / B, B>>>(N);
    k_norm<<<(E + B - 1) / B, B>>>(E);

    k_gemm1<<<(N + 31) / 32, 256>>>(x, W1, N);

    k_self<<<(N * HDIM + B - 1) / B, B>>>(N, 0);
    k_prop<<<(E * 4 + B - 1) / B, B>>>(E, 0);
    k_biasrelu<<<(N * HDIM + B - 1) / B, B>>>(b1, N);

    k_self<<<(N * HDIM + B - 1) / B, B>>>(N, 1);
    k_prop<<<(E * 4 + B - 1) / B, B>>>(E, 1);

    k_out<<<(N + B - 1) / B, B>>>(W2, b2, out, N, write_h);
}

// round 2
// speedup vs baseline: 1.1660x; 1.1660x over previous
#include <cuda_runtime.h>
#include <cstdint>

// Problem constants: N=100000, F=512, H=16, C=40, E=3200000
#define NMAX 100000
#define EMAX 3200000
#define FDIM 512
#define HDIM 16
#define CDIM 40

// ---- scratch (static device globals; no allocation allowed) ----
__device__ int    g_is64;
__device__ int2   g_edge[EMAX];        // (src, dst)
__device__ int    g_deg[NMAX];
__device__ float  g_dinv[NMAX];
__device__ float  g_h[NMAX * HDIM];    // dinv-scaled hidden (gather table)
__device__ float  g_agg1[NMAX * HDIM]; // layer-1 accumulator (init = g_h)
__device__ float  g_agg2[NMAX * HDIM]; // layer-2 accumulator (init = scaled relu)

// ---------------------------------------------------------------
// Zero degree array; thread 0 also detects int64 vs int32 edge buffer.
// Node ids < 2^31, so little-endian int64 storage has every odd 32-bit
// word equal to 0 across 128 consecutive edges (prob ~0 for int32 ids).
__global__ void k_init(const int* __restrict__ ei, int N) {
    int i = blockIdx.x * blockDim.x + threadIdx.x;
    if (i < N) g_deg[i] = 0;
    if (i == 0) {
        int any = 0;
        #pragma unroll
        for (int q = 1; q < 256; q += 2) any |= ei[q];
        g_is64 = (any == 0) ? 1 : 0;
    }
}

// Normalize edges to packed int2 and count in-degree (dst side).
__global__ __launch_bounds__(256) void k_convert(const void* __restrict__ ei, int E) {
    int e = blockIdx.x * blockDim.x + threadIdx.x;
    if (e >= E) return;
    int s, d;
    if (g_is64) {
        const long long* p = (const long long*)ei;
        s = (int)p[e];
        d = (int)p[(long long)E + e];
    } else {
        const int* p = (const int*)ei;
        s = p[e];
        d = p[E + e];
    }
    g_edge[e] = make_int2(s, d);
    atomicAdd(&g_deg[d], 1);
}

__global__ void k_dinv(int N) {
    int i = blockIdx.x * blockDim.x + threadIdx.x;
    if (i < N) g_dinv[i] = rsqrtf((float)(g_deg[i] + 1));  // +1 self-loop
}

// ---------------------------------------------------------------
// GEMM1 + scale epilogue:
//   hs[i,:] = dinv[i] * (x[i,:] @ W1)
// written to BOTH g_h (gather table) and g_agg1 (self-loop init).
// Block = 256 threads = 8 warps; warp computes 4 rows. W1 in shared
// with odd pitch 17 -> lane-stride-1 k access is bank-conflict-free.
__global__ __launch_bounds__(256) void k_gemm1(
    const float* __restrict__ x, const float* __restrict__ W1, int N)
{
    __shared__ float w[FDIM * 17];
    for (int i = threadIdx.x; i < FDIM * HDIM; i += 256)
        w[(i >> 4) * 17 + (i & 15)] = W1[i];
    __syncthreads();

    int warp = threadIdx.x >> 5;
    int lane = threadIdx.x & 31;
    int r0 = blockIdx.x * 32 + warp * 4;

    float acc[4][HDIM];
    #pragma unroll
    for (int r = 0; r < 4; r++)
        #pragma unroll
        for (int j = 0; j < HDIM; j++) acc[r][j] = 0.0f;

    bool v0 = (r0 + 0) < N, v1 = (r0 + 1) < N, v2 = (r0 + 2) < N, v3 = (r0 + 3) < N;

    #pragma unroll 4
    for (int i = 0; i < 16; i++) {
        int k = lane + 32 * i;
        float x0 = v0 ? x[(size_t)(r0 + 0) * FDIM + k] : 0.0f;
        float x1 = v1 ? x[(size_t)(r0 + 1) * FDIM + k] : 0.0f;
        float x2 = v2 ? x[(size_t)(r0 + 2) * FDIM + k] : 0.0f;
        float x3 = v3 ? x[(size_t)(r0 + 3) * FDIM + k] : 0.0f;
        const float* wr = &w[k * 17];
        #pragma unroll
        for (int j = 0; j < HDIM; j++) {
            float wv = wr[j];
            acc[0][j] += x0 * wv;
            acc[1][j] += x1 * wv;
            acc[2][j] += x2 * wv;
            acc[3][j] += x3 * wv;
        }
    }

    #pragma unroll
    for (int r = 0; r < 4; r++)
        #pragma unroll
        for (int j = 0; j < HDIM; j++)
            #pragma unroll
            for (int off = 16; off; off >>= 1)
                acc[r][j] += __shfl_xor_sync(0xffffffffu, acc[r][j], off);

    // 64 outputs, 32 lanes -> 2 writes per lane; scale by dinv[row]
    #pragma unroll
    for (int q = 0; q < 2; q++) {
        int idx = lane + 32 * q;
        int r = idx >> 4, j = idx & 15;
        int row = r0 + r;
        if (row < N) {
            float v = acc[r][j] * g_dinv[row];
            g_h[(size_t)row * HDIM + j] = v;
            g_agg1[(size_t)row * HDIM + j] = v;   // self-loop init
        }
    }
}

// ---------------------------------------------------------------
// Edge propagation: 4 threads per edge, one float4 chunk each.
// agg[dst] += hs[src]   (no norm: hs is pre-scaled, post-scale later)
__global__ __launch_bounds__(256) void k_prop(int E, int layer) {
    int t = blockIdx.x * blockDim.x + threadIdx.x;
    int e = t >> 2;
    if (e >= E) return;
    int c = t & 3;
    const float4* hin = (const float4*)g_h;
    float* out = layer ? g_agg2 : g_agg1;

    int2 sd = g_edge[e];
    float4 v = hin[(size_t)sd.x * 4 + c];
    float* p = out + (size_t)sd.y * HDIM + c * 4;
    asm volatile("red.global.add.v4.f32 [%0], {%1, %2, %3, %4};"
                 :: "l"(p), "f"(v.x), "f"(v.y), "f"(v.z), "f"(v.w)
                 : "memory");
}

// ---------------------------------------------------------------
// Mid layer: out1 = relu(dinv[i]*agg1 + b1); hs2 = dinv[i]*out1
// written to BOTH g_h (gather table) and g_agg2 (self-loop init).
__global__ void k_mid(const float* __restrict__ b1, int N) {
    int idx = blockIdx.x * blockDim.x + threadIdx.x;
    if (idx >= N * HDIM) return;
    int i = idx >> 4;
    float dv = g_dinv[i];
    float v = dv * g_agg1[idx] + b1[idx & 15];
    v = v > 0.0f ? v : 0.0f;
    v *= dv;
    g_h[idx] = v;
    g_agg2[idx] = v;
}

// ---------------------------------------------------------------
// Output: logits = (dinv[i]*agg2[i,:]) @ W2 + b2 ; out = softmax
// d_out[0 : N*40) = softmax ; d_out[N*40 : 2*N*40) = logits
__global__ __launch_bounds__(256) void k_out(
    const float* __restrict__ W2, const float* __restrict__ b2,
    float* __restrict__ dout, int N, int write_h)
{
    __shared__ float w[HDIM * CDIM];
    __shared__ float bs[CDIM];
    for (int i = threadIdx.x; i < HDIM * CDIM; i += blockDim.x) w[i] = W2[i];
    if (threadIdx.x < CDIM) bs[threadIdx.x] = b2[threadIdx.x];
    __syncthreads();

    int i = blockIdx.x * blockDim.x + threadIdx.x;
    if (i >= N) return;

    float dv = g_dinv[i];
    float row[HDIM];
    const float4* p = (const float4*)(g_agg2 + (size_t)i * HDIM);
    #pragma unroll
    for (int q = 0; q < 4; q++) {
        float4 v = p[q];
        row[q * 4 + 0] = v.x * dv; row[q * 4 + 1] = v.y * dv;
        row[q * 4 + 2] = v.z * dv; row[q * 4 + 3] = v.w * dv;
    }

    float logit[CDIM];
    #pragma unroll
    for (int j = 0; j < CDIM; j++) logit[j] = bs[j];
    #pragma unroll
    for (int k = 0; k < HDIM; k++) {
        float v = row[k];
        const float* wr = &w[k * CDIM];
        #pragma unroll
        for (int j = 0; j < CDIM; j++) logit[j] += v * wr[j];
    }

    float mx = logit[0];
    #pragma unroll
    for (int j = 1; j < CDIM; j++) mx = fmaxf(mx, logit[j]);
    float sum = 0.0f;
    #pragma unroll
    for (int j = 0; j < CDIM; j++) sum += __expf(logit[j] - mx);
    float inv = 1.0f / sum;

    float* so = dout + (size_t)i * CDIM;
    #pragma unroll
    for (int j = 0; j < CDIM; j++) so[j] = __expf(logit[j] - mx) * inv;

    if (write_h) {
        float* ho = dout + (size_t)N * CDIM + (size_t)i * CDIM;
        #pragma unroll
        for (int j = 0; j < CDIM; j++) ho[j] = logit[j];
    }
}

// ---------------------------------------------------------------
extern "C" void kernel_launch(void* const* d_in, const int* in_sizes, int n_in,
                              void* d_out, int out_size)
{
    // metadata order: x, edge_index, num_nodes, W1, b1, W2, b2
    const float* x  = (const float*)d_in[0];
    const void*  ei = d_in[1];
    const float* W1 = (const float*)d_in[3];
    const float* b1 = (const float*)d_in[4];
    const float* W2 = (const float*)d_in[5];
    const float* b2 = (const float*)d_in[6];
    float* out = (float*)d_out;

    int N = in_sizes[0] / FDIM;
    int E = in_sizes[1] / 2;
    if (N > NMAX) N = NMAX;
    if (E > EMAX) E = EMAX;
    int write_h = (out_size >= 2 * N * CDIM) ? 1 : 0;

    const int B = 256;

    k_init<<<(N + B - 1) / B, B>>>((const int*)ei, N);
    k_convert<<<(E + B - 1) / B, B>>>(ei, E);
    k_dinv<<<(N + B - 1) / B, B>>>(N);

    k_gemm1<<<(N + 31) / 32, 256>>>(x, W1, N);

    k_prop<<<((size_t)E * 4 + B - 1) / B, B>>>(E, 0);
    k_mid<<<(N * HDIM + B - 1) / B, B>>>(b1, N);
    k_prop<<<((size_t)E * 4 + B - 1) / B, B>>>(E, 1);

    k_out<<<(N + B - 1) / B, B>>>(W2, b2, out, N, write_h);
}

// round 3
// speedup vs baseline: 1.3565x; 1.1634x over previous
#include <cuda_runtime.h>
#include <cstdint>

// Problem constants: N=100000, F=512, H=16, C=40, E=3200000
#define NMAX 100000
#define EMAX 3200000
#define FDIM 512
#define HDIM 16
#define CDIM 40

// ---- scratch (static device globals; no allocation allowed) ----
__device__ int    g_is64;
__device__ int2   g_edge[EMAX];        // (src, dst)
__device__ int    g_deg[NMAX];
__device__ float  g_dinv[NMAX];
__device__ float  g_h[NMAX * HDIM];    // dinv-scaled hidden (gather table)
__device__ float  g_agg1[NMAX * HDIM]; // layer-1 accumulator (init = g_h)
__device__ float  g_agg2[NMAX * HDIM]; // layer-2 accumulator (init = scaled relu)

// ---- f32x2 packed-math helpers (sm_103a) ----
__device__ __forceinline__ unsigned long long f2_fma(
    unsigned long long a, unsigned long long b, unsigned long long c) {
    unsigned long long d;
    asm("fma.rn.f32x2 %0, %1, %2, %3;" : "=l"(d) : "l"(a), "l"(b), "l"(c));
    return d;
}
__device__ __forceinline__ unsigned long long f2_add(
    unsigned long long a, unsigned long long b) {
    unsigned long long d;
    asm("add.rn.f32x2 %0, %1, %2;" : "=l"(d) : "l"(a), "l"(b));
    return d;
}
__device__ __forceinline__ unsigned long long f2_mul(
    unsigned long long a, unsigned long long b) {
    unsigned long long d;
    asm("mul.rn.f32x2 %0, %1, %2;" : "=l"(d) : "l"(a), "l"(b));
    return d;
}
__device__ __forceinline__ unsigned long long f2_pack(float lo, float hi) {
    unsigned long long d;
    asm("mov.b64 %0, {%1, %2};" : "=l"(d) : "f"(lo), "f"(hi));
    return d;
}

// ---------------------------------------------------------------
// Zero degree array; thread 0 also detects int64 vs int32 edge buffer.
__global__ void k_init(const int* __restrict__ ei, int N) {
    int i = blockIdx.x * blockDim.x + threadIdx.x;
    if (i < N) g_deg[i] = 0;
    if (i == 0) {
        int any = 0;
        #pragma unroll
        for (int q = 1; q < 256; q += 2) any |= ei[q];
        g_is64 = (any == 0) ? 1 : 0;
    }
}

// Normalize edges to packed int2 and count in-degree (dst side).
__global__ __launch_bounds__(256) void k_convert(const void* __restrict__ ei, int E) {
    int e = blockIdx.x * blockDim.x + threadIdx.x;
    if (e >= E) return;
    int s, d;
    if (g_is64) {
        const long long* p = (const long long*)ei;
        s = (int)p[e];
        d = (int)p[(long long)E + e];
    } else {
        const int* p = (const int*)ei;
        s = p[e];
        d = p[E + e];
    }
    g_edge[e] = make_int2(s, d);
    atomicAdd(&g_deg[d], 1);
}

__global__ void k_dinv(int N) {
    int i = blockIdx.x * blockDim.x + threadIdx.x;
    if (i < N) g_dinv[i] = rsqrtf((float)(g_deg[i] + 1));  // +1 self-loop
}

// ---------------------------------------------------------------
// GEMM1 + scale epilogue:  hs[i,:] = dinv[i] * (x[i,:] @ W1)
// dual-written to g_h (gather table) and g_agg1 (self-loop init).
//
// Block = 256 threads = 8 warps; warp computes 4 rows; k split across
// lanes (k = lane + 32*i). Accumulators are f32x2-packed j-pairs:
// acc[r][j2] covers outputs (2*j2, 2*j2+1). W1 staged in shared as
// float2 j-pairs: wS[j2*PITCH + k], PITCH odd -> LDS.64 conflict-free.
// Cross-lane reduction: value-halving butterfly (31 shfl.b64 total);
// final packed output index p = bitrev5(lane), r = p>>3, j2 = p&7.
#define WPITCH 513
__global__ __launch_bounds__(256, 2) void k_gemm1(
    const float* __restrict__ x, const float* __restrict__ W1, int N)
{
    __shared__ unsigned long long wS[8 * WPITCH];

    // stage W1: float2 element idx = k*8 + j2  (W1 row-major [512][16])
    {
        const unsigned long long* gw = (const unsigned long long*)W1;
        for (int idx = threadIdx.x; idx < FDIM * 8; idx += 256) {
            int k = idx >> 3, j2 = idx & 7;
            wS[j2 * WPITCH + k] = gw[idx];
        }
    }
    __syncthreads();

    int warp = threadIdx.x >> 5;
    int lane = threadIdx.x & 31;
    int r0 = blockIdx.x * 32 + warp * 4;

    unsigned long long acc[4][8];
    #pragma unroll
    for (int r = 0; r < 4; r++)
        #pragma unroll
        for (int j = 0; j < 8; j++) acc[r][j] = 0ull;

    bool v0 = (r0 + 0) < N, v1 = (r0 + 1) < N, v2 = (r0 + 2) < N, v3 = (r0 + 3) < N;
    const float* x0p = x + (size_t)(r0 + 0) * FDIM + lane;
    const float* x1p = x + (size_t)(r0 + 1) * FDIM + lane;
    const float* x2p = x + (size_t)(r0 + 2) * FDIM + lane;
    const float* x3p = x + (size_t)(r0 + 3) * FDIM + lane;

    #pragma unroll 4
    for (int i = 0; i < 16; i++) {
        int k = lane + 32 * i;
        float x0 = v0 ? x0p[32 * i] : 0.0f;
        float x1 = v1 ? x1p[32 * i] : 0.0f;
        float x2 = v2 ? x2p[32 * i] : 0.0f;
        float x3 = v3 ? x3p[32 * i] : 0.0f;
        unsigned long long p0 = f2_pack(x0, x0);
        unsigned long long p1 = f2_pack(x1, x1);
        unsigned long long p2 = f2_pack(x2, x2);
        unsigned long long p3 = f2_pack(x3, x3);
        #pragma unroll
        for (int j = 0; j < 8; j++) {
            unsigned long long wv = wS[j * WPITCH + k];
            acc[0][j] = f2_fma(p0, wv, acc[0][j]);
            acc[1][j] = f2_fma(p1, wv, acc[1][j]);
            acc[2][j] = f2_fma(p2, wv, acc[2][j]);
            acc[3][j] = f2_fma(p3, wv, acc[3][j]);
        }
    }

    // value-halving butterfly: 32 packed values -> 1 per lane.
    unsigned long long v[32];
    #pragma unroll
    for (int r = 0; r < 4; r++)
        #pragma unroll
        for (int j = 0; j < 8; j++) v[r * 8 + j] = acc[r][j];

    #pragma unroll
    for (int s = 0; s < 5; s++) {
        const int m = 1 << s;          // xor mask this round
        const int half = 16 >> s;      // values kept after this round
        bool up = (lane & m) != 0;
        #pragma unroll
        for (int q = 0; q < 16; q++) { // constant trip count; guard by half
            if (q < half) {
                unsigned long long keep = up ? v[q + half] : v[q];
                unsigned long long mine = up ? v[q] : v[q + half];
                unsigned long long got = __shfl_xor_sync(0xffffffffu, mine, m);
                v[q] = f2_add(keep, got);
            }
        }
    }

    // p = bitrev5(lane): round m=1 fixed bit4 ... m=16 fixed bit0
    int p = ((lane & 1) << 4) | ((lane & 2) << 2) | (lane & 4) |
            ((lane & 8) >> 2) | ((lane & 16) >> 4);
    int r = p >> 3, j2 = p & 7;
    int row = r0 + r;
    if (row < N) {
        float dv = g_dinv[row];
        unsigned long long res = f2_mul(v[0], f2_pack(dv, dv));
        size_t off = (size_t)row * 8 + j2;  // float2 index
        ((unsigned long long*)g_h)[off] = res;
        ((unsigned long long*)g_agg1)[off] = res;
    }
}

// ---------------------------------------------------------------
// Edge propagation: 4 threads per edge, one float4 chunk each.
__global__ __launch_bounds__(256) void k_prop(int E, int layer) {
    int t = blockIdx.x * blockDim.x + threadIdx.x;
    int e = t >> 2;
    if (e >= E) return;
    int c = t & 3;
    const float4* hin = (const float4*)g_h;
    float* out = layer ? g_agg2 : g_agg1;

    int2 sd = g_edge[e];
    float4 v = hin[(size_t)sd.x * 4 + c];
    float* p = out + (size_t)sd.y * HDIM + c * 4;
    asm volatile("red.global.add.v4.f32 [%0], {%1, %2, %3, %4};"
                 :: "l"(p), "f"(v.x), "f"(v.y), "f"(v.z), "f"(v.w)
                 : "memory");
}

// ---------------------------------------------------------------
// Mid layer: out1 = relu(dinv[i]*agg1 + b1); hs2 = dinv[i]*out1
__global__ void k_mid(const float* __restrict__ b1, int N) {
    int idx = blockIdx.x * blockDim.x + threadIdx.x;
    if (idx >= N * HDIM) return;
    int i = idx >> 4;
    float dv = g_dinv[i];
    float v = dv * g_agg1[idx] + b1[idx & 15];
    v = v > 0.0f ? v : 0.0f;
    v *= dv;
    g_h[idx] = v;
    g_agg2[idx] = v;
}

// ---------------------------------------------------------------
// Output: logits = (dinv[i]*agg2[i,:]) @ W2 + b2 ; out = softmax
__global__ __launch_bounds__(256) void k_out(
    const float* __restrict__ W2, const float* __restrict__ b2,
    float* __restrict__ dout, int N, int write_h)
{
    __shared__ float w[HDIM * CDIM];
    __shared__ float bs[CDIM];
    for (int i = threadIdx.x; i < HDIM * CDIM; i += blockDim.x) w[i] = W2[i];
    if (threadIdx.x < CDIM) bs[threadIdx.x] = b2[threadIdx.x];
    __syncthreads();

    int i = blockIdx.x * blockDim.x + threadIdx.x;
    if (i >= N) return;

    float dv = g_dinv[i];
    float row[HDIM];
    const float4* p = (const float4*)(g_agg2 + (size_t)i * HDIM);
    #pragma unroll
    for (int q = 0; q < 4; q++) {
        float4 v = p[q];
        row[q * 4 + 0] = v.x * dv; row[q * 4 + 1] = v.y * dv;
        row[q * 4 + 2] = v.z * dv; row[q * 4 + 3] = v.w * dv;
    }

    float logit[CDIM];
    #pragma unroll
    for (int j = 0; j < CDIM; j++) logit[j] = bs[j];
    #pragma unroll
    for (int k = 0; k < HDIM; k++) {
        float v = row[k];
        const float* wr = &w[k * CDIM];
        #pragma unroll
        for (int j = 0; j < CDIM; j++) logit[j] += v * wr[j];
    }

    float mx = logit[0];
    #pragma unroll
    for (int j = 1; j < CDIM; j++) mx = fmaxf(mx, logit[j]);
    float sum = 0.0f;
    #pragma unroll
    for (int j = 0; j < CDIM; j++) sum += __expf(logit[j] - mx);
    float inv = 1.0f / sum;

    float* so = dout + (size_t)i * CDIM;
    #pragma unroll
    for (int j = 0; j < CDIM; j++) so[j] = __expf(logit[j] - mx) * inv;

    if (write_h) {
        float* ho = dout + (size_t)N * CDIM + (size_t)i * CDIM;
        #pragma unroll
        for (int j = 0; j < CDIM; j++) ho[j] = logit[j];
    }
}

// ---------------------------------------------------------------
extern "C" void kernel_launch(void* const* d_in, const int* in_sizes, int n_in,
                              void* d_out, int out_size)
{
    // metadata order: x, edge_index, num_nodes, W1, b1, W2, b2
    const float* x  = (const float*)d_in[0];
    const void*  ei = d_in[1];
    const float* W1 = (const float*)d_in[3];
    const float* b1 = (const float*)d_in[4];
    const float* W2 = (const float*)d_in[5];
    const float* b2 = (const float*)d_in[6];
    float* out = (float*)d_out;

    int N = in_sizes[0] / FDIM;
    int E = in_sizes[1] / 2;
    if (N > NMAX) N = NMAX;
    if (E > EMAX) E = EMAX;
    int write_h = (out_size >= 2 * N * CDIM) ? 1 : 0;

    const int B = 256;

    k_init<<<(N + B - 1) / B, B>>>((const int*)ei, N);
    k_convert<<<(E + B - 1) / B, B>>>(ei, E);
    k_dinv<<<(N + B - 1) / B, B>>>(N);

    k_gemm1<<<(N + 31) / 32, 256>>>(x, W1, N);

    k_prop<<<((size_t)E * 4 + B - 1) / B, B>>>(E, 0);
    k_mid<<<(N * HDIM + B - 1) / B, B>>>(b1, N);
    k_prop<<<((size_t)E * 4 + B - 1) / B, B>>>(E, 1);

    k_out<<<(N + B - 1) / B, B>>>(W2, b2, out, N, write_h);
}